// round 3
// baseline (speedup 1.0000x reference)
#include <cuda_runtime.h>
#include <cstdint>

#define N_NODES 100000
#define E_EDGES 1600000
#define F_INPUT 128
#define HEADS   8
#define HID     8
#define F1      64        // HEADS*HID
#define N_CLS   16
#define NEG     0.2f

// -------------------- scratch (device globals; no allocation allowed) ------
// NOTE: __align__(16) is load-bearing: these are touched with float4 loads and
// red.global.add.v4.f32, which trap on <16B-aligned addresses.
__device__ __align__(16) float g_h1 [N_NODES * F1];     // layer1 linear output h = x@W1
__device__ __align__(16) float g_as1[N_NODES * HEADS];  // alpha_src per node/head
__device__ __align__(16) float g_ad1[N_NODES * HEADS];  // alpha_dst per node/head
__device__ __align__(16) float g_den1[N_NODES * HEADS]; // softmax denominators
__device__ __align__(16) float g_acc1[N_NODES * F1];    // unnormalized weighted sums
__device__ __align__(16) float g_g2 [N_NODES * N_CLS];  // layer2 linear output
__device__ __align__(16) float g_as2[N_NODES];
__device__ __align__(16) float g_ad2[N_NODES];
__device__ __align__(16) float g_den2[N_NODES];

// -------------------- helpers ---------------------------------------------
__device__ __forceinline__ void red4(float* p, float a, float b, float c, float d) {
    asm volatile("red.global.add.v4.f32 [%0], {%1,%2,%3,%4};"
                 :: "l"(p), "f"(a), "f"(b), "f"(c), "f"(d) : "memory");
}

__device__ __forceinline__ unsigned long long ffma2(unsigned long long a,
                                                    unsigned long long b,
                                                    unsigned long long c) {
    unsigned long long d;
    asm("fma.rn.f32x2 %0, %1, %2, %3;" : "=l"(d) : "l"(a), "l"(b), "l"(c));
    return d;
}

__device__ __forceinline__ unsigned long long pack2(float v) {
    unsigned long long r;
    asm("mov.b64 %0, {%1,%1};" : "=l"(r) : "f"(v));
    return r;
}

__device__ __forceinline__ void unpack2(unsigned long long v, float& lo, float& hi) {
    asm("mov.b64 {%0,%1}, %2;" : "=f"(lo), "=f"(hi) : "l"(v));
}

// -------------------- K0: zero accumulators -------------------------------
__global__ void zero_kernel(float* __restrict__ out2) {
    int i = blockIdx.x * blockDim.x + threadIdx.x;
    int stride = gridDim.x * blockDim.x;
    for (int j = i; j < N_NODES * F1;    j += stride) g_acc1[j] = 0.f;
    for (int j = i; j < N_NODES * HEADS; j += stride) g_den1[j] = 0.f;
    for (int j = i; j < N_NODES;         j += stride) g_den2[j] = 0.f;
    for (int j = i; j < N_NODES * N_CLS; j += stride) out2[j]  = 0.f;
}

// -------------------- K1: h1 = x@W1 + per-node attention dots -------------
// 256 threads, 32 rows/block. Thread = (row, head). Packed f32x2 FMAs.
__global__ __launch_bounds__(256) void gemm1_kernel(
    const float* __restrict__ x,  const float* __restrict__ W1,
    const float* __restrict__ a1s, const float* __restrict__ a1d)
{
    __shared__ float Ws[F_INPUT * F1];   // 32 KB
    __shared__ float xs[32 * F_INPUT];   // 16 KB  (total exactly 48 KB)
    int tid = threadIdx.x;
    {
        const float4* w4 = (const float4*)W1;
        float4* ws4 = (float4*)Ws;
        for (int i = tid; i < F_INPUT * F1 / 4; i += 256) ws4[i] = w4[i];
        const float4* x4 = (const float4*)(x + (size_t)blockIdx.x * 32 * F_INPUT);
        float4* xs4 = (float4*)xs;
        for (int i = tid; i < 32 * F_INPUT / 4; i += 256) xs4[i] = x4[i];
    }
    __syncthreads();

    int r  = tid >> 3;   // 0..31 row within tile
    int og = tid & 7;    // head (8 outputs each)
    unsigned long long acc2[4];
#pragma unroll
    for (int j = 0; j < 4; j++) acc2[j] = pack2(0.f);

#pragma unroll 4
    for (int k = 0; k < F_INPUT; k++) {
        unsigned long long xv2 = pack2(xs[r * F_INPUT + k]);
        const ulonglong2* w2p = (const ulonglong2*)(Ws + k * F1 + og * 8);
        ulonglong2 wa = w2p[0], wb = w2p[1];
        acc2[0] = ffma2(xv2, wa.x, acc2[0]);
        acc2[1] = ffma2(xv2, wa.y, acc2[1]);
        acc2[2] = ffma2(xv2, wb.x, acc2[2]);
        acc2[3] = ffma2(xv2, wb.y, acc2[3]);
    }
    float acc[8];
#pragma unroll
    for (int j = 0; j < 4; j++) unpack2(acc2[j], acc[2*j], acc[2*j+1]);

    float as = 0.f, ad = 0.f;
#pragma unroll
    for (int j = 0; j < 8; j++) {
        as += acc[j] * __ldg(a1s + og * 8 + j);
        ad += acc[j] * __ldg(a1d + og * 8 + j);
    }
    int n = blockIdx.x * 32 + r;
    float4* h4 = (float4*)(g_h1 + (size_t)n * F1 + og * 8);
    h4[0] = make_float4(acc[0], acc[1], acc[2], acc[3]);
    h4[1] = make_float4(acc[4], acc[5], acc[6], acc[7]);
    g_as1[n * HEADS + og] = as;
    g_ad1[n * HEADS + og] = ad;
}

// -------------------- K2: layer-1 edge pass (single pass, deferred norm) --
__global__ __launch_bounds__(256) void edge1_kernel(
    const int* __restrict__ src, const int* __restrict__ dst)
{
    int e = blockIdx.x * blockDim.x + threadIdx.x;
    if (e >= E_EDGES) return;
    int s = src[e], d = dst[e];

    const float4* as4 = (const float4*)g_as1;
    const float4* ad4 = (const float4*)g_ad1;
    float4 sa = as4[(size_t)s * 2 + 0], sb = as4[(size_t)s * 2 + 1];
    float4 da = ad4[(size_t)d * 2 + 0], db = ad4[(size_t)d * 2 + 1];

    float w[8];
    float ev;
    ev = sa.x + da.x; ev = fmaxf(ev, NEG * ev); w[0] = __expf(ev);
    ev = sa.y + da.y; ev = fmaxf(ev, NEG * ev); w[1] = __expf(ev);
    ev = sa.z + da.z; ev = fmaxf(ev, NEG * ev); w[2] = __expf(ev);
    ev = sa.w + da.w; ev = fmaxf(ev, NEG * ev); w[3] = __expf(ev);
    ev = sb.x + db.x; ev = fmaxf(ev, NEG * ev); w[4] = __expf(ev);
    ev = sb.y + db.y; ev = fmaxf(ev, NEG * ev); w[5] = __expf(ev);
    ev = sb.z + db.z; ev = fmaxf(ev, NEG * ev); w[6] = __expf(ev);
    ev = sb.w + db.w; ev = fmaxf(ev, NEG * ev); w[7] = __expf(ev);

    red4(g_den1 + (size_t)d * HEADS,     w[0], w[1], w[2], w[3]);
    red4(g_den1 + (size_t)d * HEADS + 4, w[4], w[5], w[6], w[7]);

    const float4* h4 = (const float4*)(g_h1 + (size_t)s * F1);
    float* accp = g_acc1 + (size_t)d * F1;
#pragma unroll
    for (int j = 0; j < 16; j++) {
        float4 hv = h4[j];
        float ww = w[j >> 1];
        red4(accp + j * 4, ww * hv.x, ww * hv.y, ww * hv.z, ww * hv.w);
    }
}

// -------------------- K3: normalize + bias + ELU + layer2 linear + dots ---
// 128 threads = 8 nodes x 16 lanes (one lane per output class)
__global__ __launch_bounds__(128) void node2_kernel(
    const float* __restrict__ b1, const float* __restrict__ W2,
    const float* __restrict__ a2s, const float* __restrict__ a2d)
{
    __shared__ float W2s[F1 * N_CLS];     // 4 KB
    __shared__ float h2s[8][F1];
    __shared__ float b1s[F1];
    int tid = threadIdx.x;
    for (int i = tid; i < F1 * N_CLS; i += 128) W2s[i] = W2[i];
    if (tid < F1) b1s[tid] = b1[tid];
    __syncthreads();

    int gI = tid >> 4;   // node within block
    int c  = tid & 15;   // class
    int n  = blockIdx.x * 8 + gI;

#pragma unroll
    for (int i = 0; i < 4; i++) {
        int k = c + 16 * i;
        float den = g_den1[(size_t)n * HEADS + (k >> 3)];
        float v = den > 0.f ? g_acc1[(size_t)n * F1 + k] / den : 0.f;
        v += b1s[k];
        v = v > 0.f ? v : expm1f(v);   // ELU
        h2s[gI][k] = v;
    }
    __syncthreads();

    float gc = 0.f;
#pragma unroll
    for (int k = 0; k < F1; k++) gc += h2s[gI][k] * W2s[k * N_CLS + c];
    g_g2[(size_t)n * N_CLS + c] = gc;

    float sv = gc * __ldg(a2s + c);
    float dv = gc * __ldg(a2d + c);
#pragma unroll
    for (int off = 8; off >= 1; off >>= 1) {
        sv += __shfl_xor_sync(0xFFFFFFFFu, sv, off);
        dv += __shfl_xor_sync(0xFFFFFFFFu, dv, off);
    }
    if (c == 0) { g_as2[n] = sv; g_ad2[n] = dv; }
}

// -------------------- K4: layer-2 edge pass -------------------------------
__global__ __launch_bounds__(256) void edge2_kernel(
    const int* __restrict__ src, const int* __restrict__ dst,
    float* __restrict__ out2)
{
    int e = blockIdx.x * blockDim.x + threadIdx.x;
    if (e >= E_EDGES) return;
    int s = src[e], d = dst[e];
    float ev = g_as2[s] + g_ad2[d];
    ev = fmaxf(ev, NEG * ev);
    float w = __expf(ev);
    atomicAdd(g_den2 + d, w);
    const float4* g4 = (const float4*)(g_g2 + (size_t)s * N_CLS);
    float* op = out2 + (size_t)d * N_CLS;
#pragma unroll
    for (int j = 0; j < 4; j++) {
        float4 v = g4[j];
        red4(op + j * 4, w * v.x, w * v.y, w * v.z, w * v.w);
    }
}

// -------------------- K5: normalize + bias + log_softmax ------------------
__global__ __launch_bounds__(128) void final_kernel(
    float* __restrict__ out2, const float* __restrict__ b2)
{
    int tid = threadIdx.x;
    int gI = tid >> 4, c = tid & 15;
    int n = blockIdx.x * 8 + gI;
    float den = g_den2[n];
    float v = den > 0.f ? out2[(size_t)n * N_CLS + c] / den : 0.f;
    v += __ldg(b2 + c);
    float m = v;
#pragma unroll
    for (int off = 8; off >= 1; off >>= 1)
        m = fmaxf(m, __shfl_xor_sync(0xFFFFFFFFu, m, off));
    float ex = __expf(v - m);
#pragma unroll
    for (int off = 8; off >= 1; off >>= 1)
        ex += __shfl_xor_sync(0xFFFFFFFFu, ex, off);
    out2[(size_t)n * N_CLS + c] = v - m - __logf(ex);
}

// -------------------- launch ----------------------------------------------
extern "C" void kernel_launch(void* const* d_in, const int* in_sizes, int n_in,
                              void* d_out, int out_size)
{
    const float* x   = (const float*)d_in[0];
    const int*   ei  = (const int*)  d_in[1];
    const float* W1  = (const float*)d_in[2];
    const float* a1s = (const float*)d_in[3];
    const float* a1d = (const float*)d_in[4];
    const float* b1  = (const float*)d_in[5];
    const float* W2  = (const float*)d_in[6];
    const float* a2s = (const float*)d_in[7];
    const float* a2d = (const float*)d_in[8];
    const float* b2  = (const float*)d_in[9];
    const int* src = ei;
    const int* dst = ei + E_EDGES;
    float* out = (float*)d_out;

    zero_kernel <<<2048, 256>>>(out);
    gemm1_kernel<<<N_NODES / 32, 256>>>(x, W1, a1s, a1d);
    edge1_kernel<<<E_EDGES / 256, 256>>>(src, dst);
    node2_kernel<<<N_NODES / 8, 128>>>(b1, W2, a2s, a2d);
    edge2_kernel<<<E_EDGES / 256, 256>>>(src, dst, out);
    final_kernel<<<N_NODES / 8, 128>>>(out, b2);
}

// round 6
// speedup vs baseline: 1.4817x; 1.4817x over previous
#include <cuda_runtime.h>
#include <cstdint>

#define N_NODES 100000
#define E_EDGES 1600000
#define F_INPUT 128
#define HEADS   8
#define HID     8
#define F1      64
#define N_CLS   16
#define NEG     0.2f

#define SCAN_CHUNK 1024
#define NB_SCAN ((N_NODES + SCAN_CHUNK - 1) / SCAN_CHUNK)   // 98

// -------------------- scratch ----------------------------------------------
__device__ __align__(16) float g_h1 [N_NODES * F1];
__device__ __align__(16) float g_h2 [N_NODES * F1];
__device__ __align__(16) float g_as1[N_NODES * HEADS];
__device__ __align__(16) float g_ad1[N_NODES * HEADS];
__device__ __align__(16) float g_g2 [N_NODES * N_CLS];
__device__ __align__(16) float g_as2[N_NODES];
__device__ __align__(16) float g_ad2[N_NODES];
__device__ int g_cnt[N_NODES];
__device__ int g_rp [N_NODES + 1];
__device__ int g_wp [N_NODES];
__device__ int g_part[NB_SCAN];
__device__ int g_poff[NB_SCAN];
__device__ int g_esrc[E_EDGES];

// -------------------- helpers ----------------------------------------------
__device__ __forceinline__ unsigned long long ffma2(unsigned long long a,
                                                    unsigned long long b,
                                                    unsigned long long c) {
    unsigned long long d;
    asm("fma.rn.f32x2 %0, %1, %2, %3;" : "=l"(d) : "l"(a), "l"(b), "l"(c));
    return d;
}
__device__ __forceinline__ unsigned long long pack2(float v) {
    unsigned long long r;
    asm("mov.b64 %0, {%1,%1};" : "=l"(r) : "f"(v));
    return r;
}
__device__ __forceinline__ void unpack2(unsigned long long v, float& lo, float& hi) {
    asm("mov.b64 {%0,%1}, %2;" : "=f"(lo), "=f"(hi) : "l"(v));
}

// -------------------- K0: zero counts --------------------------------------
__global__ void zero_cnt_kernel() {
    int i = blockIdx.x * blockDim.x + threadIdx.x;
    if (i < N_NODES) g_cnt[i] = 0;
}

// -------------------- K1: h1 = x@W1 + attention dots ------------------------
__global__ __launch_bounds__(256) void gemm1_kernel(
    const float* __restrict__ x,  const float* __restrict__ W1,
    const float* __restrict__ a1s, const float* __restrict__ a1d)
{
    __shared__ float Ws[F_INPUT * F1];   // 32 KB
    __shared__ float xs[32 * F_INPUT];   // 16 KB
    int tid = threadIdx.x;
    {
        const float4* w4 = (const float4*)W1;
        float4* ws4 = (float4*)Ws;
        for (int i = tid; i < F_INPUT * F1 / 4; i += 256) ws4[i] = w4[i];
        const float4* x4 = (const float4*)(x + (size_t)blockIdx.x * 32 * F_INPUT);
        float4* xs4 = (float4*)xs;
        for (int i = tid; i < 32 * F_INPUT / 4; i += 256) xs4[i] = x4[i];
    }
    __syncthreads();

    int r  = tid >> 3;
    int og = tid & 7;
    unsigned long long acc2[4];
#pragma unroll
    for (int j = 0; j < 4; j++) acc2[j] = pack2(0.f);

#pragma unroll 4
    for (int k = 0; k < F_INPUT; k++) {
        unsigned long long xv2 = pack2(xs[r * F_INPUT + k]);
        const ulonglong2* w2p = (const ulonglong2*)(Ws + k * F1 + og * 8);
        ulonglong2 wa = w2p[0], wb = w2p[1];
        acc2[0] = ffma2(xv2, wa.x, acc2[0]);
        acc2[1] = ffma2(xv2, wa.y, acc2[1]);
        acc2[2] = ffma2(xv2, wb.x, acc2[2]);
        acc2[3] = ffma2(xv2, wb.y, acc2[3]);
    }
    float acc[8];
#pragma unroll
    for (int j = 0; j < 4; j++) unpack2(acc2[j], acc[2*j], acc[2*j+1]);

    float as = 0.f, ad = 0.f;
#pragma unroll
    for (int j = 0; j < 8; j++) {
        as += acc[j] * __ldg(a1s + og * 8 + j);
        ad += acc[j] * __ldg(a1d + og * 8 + j);
    }
    int n = blockIdx.x * 32 + r;
    float4* h4 = (float4*)(g_h1 + (size_t)n * F1 + og * 8);
    h4[0] = make_float4(acc[0], acc[1], acc[2], acc[3]);
    h4[1] = make_float4(acc[4], acc[5], acc[6], acc[7]);
    g_as1[n * HEADS + og] = as;
    g_ad1[n * HEADS + og] = ad;
}

// -------------------- CSR build ---------------------------------------------
__global__ void hist_kernel(const int* __restrict__ dst) {
    int e = blockIdx.x * blockDim.x + threadIdx.x;
    if (e < E_EDGES) atomicAdd(&g_cnt[dst[e]], 1);
}

__global__ __launch_bounds__(SCAN_CHUNK) void scanA_kernel() {
    __shared__ int s[SCAN_CHUNK];
    int tid = threadIdx.x;
    int i = blockIdx.x * SCAN_CHUNK + tid;
    int v = (i < N_NODES) ? g_cnt[i] : 0;
    s[tid] = v;
    __syncthreads();
#pragma unroll
    for (int off = 1; off < SCAN_CHUNK; off <<= 1) {
        int t = (tid >= off) ? s[tid - off] : 0;
        __syncthreads();
        s[tid] += t;
        __syncthreads();
    }
    if (i < N_NODES) g_rp[i] = s[tid] - v;          // exclusive within block
    if (tid == SCAN_CHUNK - 1) g_part[blockIdx.x] = s[tid];
}

__global__ void scanB_kernel() {
    if (threadIdx.x == 0) {
        int run = 0;
        for (int b = 0; b < NB_SCAN; b++) { g_poff[b] = run; run += g_part[b]; }
    }
}

__global__ void scanC_kernel() {
    int i = blockIdx.x * blockDim.x + threadIdx.x;
    if (i < N_NODES) {
        int v = g_rp[i] + g_poff[i / SCAN_CHUNK];
        g_rp[i] = v;
        g_wp[i] = v;
    }
    if (i == 0) g_rp[N_NODES] = E_EDGES;
}

__global__ void scatter_kernel(const int* __restrict__ src, const int* __restrict__ dst) {
    int e = blockIdx.x * blockDim.x + threadIdx.x;
    if (e < E_EDGES) {
        int pos = atomicAdd(&g_wp[dst[e]], 1);
        g_esrc[pos] = src[e];
    }
}

// -------------------- gather1: layer-1 aggregate + norm + bias + ELU --------
// One warp per dst node. Lane owns dims {2*lane, 2*lane+1}; head = lane>>2.
__global__ __launch_bounds__(256) void gather1_kernel(const float* __restrict__ b1)
{
    int n = (blockIdx.x * 256 + threadIdx.x) >> 5;
    int lane = threadIdx.x & 31;
    int h = lane >> 2;
    int beg = g_rp[n], end = g_rp[n + 1];
    float ad = g_ad1[n * HEADS + h];

    float ax = 0.f, ay = 0.f, den = 0.f;
#pragma unroll 4
    for (int i = beg; i < end; i++) {
        int s = g_esrc[i];
        float ev = g_as1[s * HEADS + h] + ad;
        ev = fmaxf(ev, NEG * ev);
        float w = __expf(ev);
        float2 hv = *(const float2*)(g_h1 + (size_t)s * F1 + lane * 2);
        ax += w * hv.x;
        ay += w * hv.y;
        den += w;
    }
    float r = (den > 0.f) ? (1.f / den) : 0.f;
    float v0 = ax * r + __ldg(b1 + lane * 2);
    float v1 = ay * r + __ldg(b1 + lane * 2 + 1);
    v0 = v0 > 0.f ? v0 : (__expf(v0) - 1.f);   // ELU
    v1 = v1 > 0.f ? v1 : (__expf(v1) - 1.f);
    *(float2*)(g_h2 + (size_t)n * F1 + lane * 2) = make_float2(v0, v1);
}

// -------------------- node2: g2 = h2@W2 + layer-2 attention dots ------------
__global__ __launch_bounds__(128) void node2_kernel(
    const float* __restrict__ W2,
    const float* __restrict__ a2s, const float* __restrict__ a2d)
{
    __shared__ float W2s[F1 * N_CLS];   // 4 KB
    __shared__ float h2s[8][F1];
    int tid = threadIdx.x;
    for (int i = tid; i < F1 * N_CLS; i += 128) W2s[i] = W2[i];
    __syncthreads();

    int gI = tid >> 4;
    int c  = tid & 15;
    int n  = blockIdx.x * 8 + gI;

#pragma unroll
    for (int i = 0; i < 4; i++) {
        int k = c + 16 * i;
        h2s[gI][k] = g_h2[(size_t)n * F1 + k];
    }
    __syncthreads();

    float gc = 0.f;
#pragma unroll
    for (int k = 0; k < F1; k++) gc += h2s[gI][k] * W2s[k * N_CLS + c];
    g_g2[(size_t)n * N_CLS + c] = gc;

    float sv = gc * __ldg(a2s + c);
    float dv = gc * __ldg(a2d + c);
#pragma unroll
    for (int off = 8; off >= 1; off >>= 1) {
        sv += __shfl_xor_sync(0xFFFFFFFFu, sv, off);
        dv += __shfl_xor_sync(0xFFFFFFFFu, dv, off);
    }
    if (c == 0) { g_as2[n] = sv; g_ad2[n] = dv; }
}

// -------------------- gather2: layer-2 aggregate + norm + bias + logsoftmax -
// Half-warp (16 lanes) per dst node; lane owns one class.
__global__ __launch_bounds__(256) void gather2_kernel(
    const float* __restrict__ b2, float* __restrict__ out)
{
    int gid = blockIdx.x * 256 + threadIdx.x;
    int n = gid >> 4;
    int c = threadIdx.x & 15;
    int beg = g_rp[n], end = g_rp[n + 1];
    float ad = g_ad2[n];

    float acc = 0.f, den = 0.f;
#pragma unroll 4
    for (int i = beg; i < end; i++) {
        int s = g_esrc[i];
        float ev = g_as2[s] + ad;
        ev = fmaxf(ev, NEG * ev);
        float w = __expf(ev);
        acc += w * g_g2[(size_t)s * N_CLS + c];
        den += w;
    }
    float v = (den > 0.f) ? (acc / den) : 0.f;
    v += __ldg(b2 + c);

    float m = v;
#pragma unroll
    for (int off = 8; off >= 1; off >>= 1)
        m = fmaxf(m, __shfl_xor_sync(0xFFFFFFFFu, m, off));
    float ex = __expf(v - m);
#pragma unroll
    for (int off = 8; off >= 1; off >>= 1)
        ex += __shfl_xor_sync(0xFFFFFFFFu, ex, off);
    out[(size_t)n * N_CLS + c] = v - m - __logf(ex);
}

// -------------------- launch ------------------------------------------------
extern "C" void kernel_launch(void* const* d_in, const int* in_sizes, int n_in,
                              void* d_out, int out_size)
{
    const float* x   = (const float*)d_in[0];
    const int*   ei  = (const int*)  d_in[1];
    const float* W1  = (const float*)d_in[2];
    const float* a1s = (const float*)d_in[3];
    const float* a1d = (const float*)d_in[4];
    const float* b1  = (const float*)d_in[5];
    const float* W2  = (const float*)d_in[6];
    const float* a2s = (const float*)d_in[7];
    const float* a2d = (const float*)d_in[8];
    const float* b2  = (const float*)d_in[9];
    const int* src = ei;
    const int* dst = ei + E_EDGES;
    float* out = (float*)d_out;

    zero_cnt_kernel<<<(N_NODES + 255) / 256, 256>>>();
    gemm1_kernel  <<<N_NODES / 32, 256>>>(x, W1, a1s, a1d);
    hist_kernel   <<<E_EDGES / 256, 256>>>(dst);
    scanA_kernel  <<<NB_SCAN, SCAN_CHUNK>>>();
    scanB_kernel  <<<1, 32>>>();
    scanC_kernel  <<<(N_NODES + 255) / 256, 256>>>();
    scatter_kernel<<<E_EDGES / 256, 256>>>(src, dst);
    gather1_kernel<<<N_NODES * 32 / 256, 256>>>(b1);
    node2_kernel  <<<N_NODES / 8, 128>>>(W2, a2s, a2d);
    gather2_kernel<<<N_NODES * 16 / 256, 256>>>(b2, out);
}